// round 1
// baseline (speedup 1.0000x reference)
#include <cuda_runtime.h>

typedef unsigned long long u64;
#define DEVINL __device__ __forceinline__

// ---- packed f32x2 helpers (sm_100+ PTX) ----
DEVINL u64 pk2(float x, float y) { u64 r; asm("mov.b64 %0,{%1,%2};" : "=l"(r) : "f"(x), "f"(y)); return r; }
DEVINL u64 dup2(float x) { return pk2(x, x); }
DEVINL void upk2(u64 v, float& x, float& y) { asm("mov.b64 {%0,%1},%2;" : "=f"(x), "=f"(y) : "l"(v)); }
DEVINL void fma2(u64& d, u64 a, u64 b) { asm("fma.rn.f32x2 %0,%1,%2,%0;" : "+l"(d) : "l"(a), "l"(b)); }

// ---- problem constants ----
constexpr int F = 128, DIN = 64, D = 64, H = 8;
constexpr int XT_LD = 132;             // transposed-layout row stride (pad for bank spread)
constexpr int ASD_LD = 256;            // duplicated-A row stride (128 g * 2)

// shared layout (floats)
constexpr int OFF_XT  = 0;                       // Xt[64][132]
constexpr int OFF_QT  = OFF_XT + 64 * XT_LD;     // Qt[64][132]  (Q transposed: [d][f])
constexpr int OFF_KT  = OFF_QT + 64 * XT_LD;     // Kt[64][132]  (K transposed: [d][g])
constexpr int OFF_KS  = OFF_KT + 64 * XT_LD;     // Ks[128][64]  (K row-major: [g][d])
constexpr int OFF_WS  = OFF_KS + 128 * 64;       // Ws[64][64]
constexpr int OFF_ASD = OFF_WS + 64 * 64;        // Asd[64][256]
constexpr int SMEM_FLOATS = OFF_ASD + 64 * ASD_LD;   // 54016 floats = 216064 B

// Load one head's weight [64][64] into Ws. w layout: [i][h][d] = i*512 + h*64 + d.
DEVINL void load_w(float* Ws, const float* __restrict__ wsrc, int h, int t) {
#pragma unroll
    for (int k = 0; k < 4; k++) {
        int idx4 = t + k * 256;
        int i = idx4 >> 4;
        int d4 = (idx4 & 15) * 4;
        *(float4*)&Ws[i * 64 + d4] = *(const float4*)&wsrc[i * (H * D) + h * D + d4];
    }
}

// GEMM variant A: out[f][d] = sum_i Xt[i][f] * Ws[i][d]; acc pairs along f.
// If outS != nullptr store to shared [128][64], else to global base (row-major).
DEVINL void gemmA(float* outS, float* outG, const float* Xt, const float* Ws, int t) {
    int tx = t & 15, ty = t >> 4;
    int dq = tx * 4, fo = ty * 8;
    u64 acc[4][4];
#pragma unroll
    for (int a = 0; a < 4; a++)
#pragma unroll
        for (int c = 0; c < 4; c++) acc[a][c] = 0ull;
#pragma unroll 8
    for (int i = 0; i < 64; i++) {
        u64 x2[4];
#pragma unroll
        for (int fp = 0; fp < 4; fp++) x2[fp] = *(const u64*)&Xt[i * XT_LD + fo + 2 * fp];
        float4 wv = *(const float4*)&Ws[i * 64 + dq];
        u64 wd0 = dup2(wv.x), wd1 = dup2(wv.y), wd2 = dup2(wv.z), wd3 = dup2(wv.w);
#pragma unroll
        for (int fp = 0; fp < 4; fp++) {
            fma2(acc[fp][0], x2[fp], wd0);
            fma2(acc[fp][1], x2[fp], wd1);
            fma2(acc[fp][2], x2[fp], wd2);
            fma2(acc[fp][3], x2[fp], wd3);
        }
    }
#pragma unroll
    for (int fp = 0; fp < 4; fp++)
#pragma unroll
        for (int c = 0; c < 4; c++) {
            float a0, a1;
            upk2(acc[fp][c], a0, a1);
            int r0 = fo + 2 * fp, r1 = r0 + 1, dd = dq + c;
            if (outS) { outS[r0 * 64 + dd] = a0; outS[r1 * 64 + dd] = a1; }
            else      { outG[r0 * 64 + dd] = a0; outG[r1 * 64 + dd] = a1; }
        }
}

// GEMM variant T: out[d][f] = sum_i Ws[i][d] * Xt[i][f]; acc pairs along d.
// Output stored transposed with stride XT_LD.
DEVINL void gemmT(float* outT, const float* Xt, const float* Ws, int t) {
    int lane = t & 31, w = t >> 5;
    int fq = lane * 4, do8 = w * 8;
    u64 acc[4][4];   // [dp][fc]
#pragma unroll
    for (int a = 0; a < 4; a++)
#pragma unroll
        for (int c = 0; c < 4; c++) acc[a][c] = 0ull;
#pragma unroll 8
    for (int i = 0; i < 64; i++) {
        u64 w2[4];
#pragma unroll
        for (int dp = 0; dp < 4; dp++) w2[dp] = *(const u64*)&Ws[i * 64 + do8 + 2 * dp];
        float4 xv = *(const float4*)&Xt[i * XT_LD + fq];
        u64 xd0 = dup2(xv.x), xd1 = dup2(xv.y), xd2 = dup2(xv.z), xd3 = dup2(xv.w);
#pragma unroll
        for (int dp = 0; dp < 4; dp++) {
            fma2(acc[dp][0], w2[dp], xd0);
            fma2(acc[dp][1], w2[dp], xd1);
            fma2(acc[dp][2], w2[dp], xd2);
            fma2(acc[dp][3], w2[dp], xd3);
        }
    }
#pragma unroll
    for (int dp = 0; dp < 4; dp++)
#pragma unroll
        for (int fc = 0; fc < 4; fc++) {
            float a0, a1;
            upk2(acc[dp][fc], a0, a1);
            int d0 = do8 + 2 * dp, ff = fq + fc;
            outT[d0 * XT_LD + ff] = a0;
            outT[(d0 + 1) * XT_LD + ff] = a1;
        }
}

__global__ void __launch_bounds__(256, 1)
mha_sigmoid_ln_kernel(const float* __restrict__ x,
                      const float* __restrict__ wq,
                      const float* __restrict__ wk,
                      const float* __restrict__ wr,
                      const float* __restrict__ gamma,
                      const float* __restrict__ beta,
                      float* __restrict__ out, int B) {
    extern __shared__ float sm[];
    float* Xt  = sm + OFF_XT;
    float* Qt  = sm + OFF_QT;
    float* Kt  = sm + OFF_KT;
    float* Ks  = sm + OFF_KS;
    float* Ws  = sm + OFF_WS;
    float* Asd = sm + OFF_ASD;

    const int t = threadIdx.x;
    const int lane = t & 31, w = t >> 5;
    const int h = blockIdx.x, b = blockIdx.y;
    const size_t HBFD = (size_t)H * B * F * D;

    // per-lane LN params for d = 2*lane, 2*lane+1
    const float g0 = gamma[2 * lane], g1 = gamma[2 * lane + 1];
    const float be0 = beta[2 * lane], be1 = beta[2 * lane + 1];

    // ---- load X transposed: Xt[i][f] ----
    {
        const float4* xg = (const float4*)(x + (size_t)b * F * DIN);
#pragma unroll
        for (int k = 0; k < 8; k++) {
            int idx4 = t + k * 256;
            int f = idx4 >> 4;
            int i = (idx4 & 15) * 4;
            float4 v = xg[idx4];
            Xt[(i + 0) * XT_LD + f] = v.x;
            Xt[(i + 1) * XT_LD + f] = v.y;
            Xt[(i + 2) * XT_LD + f] = v.z;
            Xt[(i + 3) * XT_LD + f] = v.w;
        }
    }
    __syncthreads();

    // ---- Q projection (transposed) ----
    load_w(Ws, wq, h, t);
    __syncthreads();
    gemmT(Qt, Xt, Ws, t);
    __syncthreads();

    // ---- K projection: both orientations (V == K per reference) ----
    load_w(Ws, wk, h, t);
    __syncthreads();
    gemmT(Kt, Xt, Ws, t);
    gemmA(Ks, nullptr, Xt, Ws, t);
    __syncthreads();

    // ---- R projection straight to global (second tuple element) ----
    load_w(Ws, wr, h, t);
    __syncthreads();
    gemmA(nullptr, out + HBFD + ((size_t)h * B + b) * (F * D), Xt, Ws, t);
    // no syncthreads needed: attention only reads Qt/Kt/Ks (published above)

    // ---- attention + LN: two passes of 64 rows, warp handles 8 rows ----
#pragma unroll 1
    for (int pass = 0; pass < 2; pass++) {
        const int fbase = pass * 64;
        const int f0 = fbase + w * 8;   // global row
        const int l0 = w * 8;           // local row in Asd

        // S = Q K^T: accS[rp][c] = (S[f0+2rp][g], S[f0+2rp+1][g]), g = lane+32c
        u64 accS[4][4];
#pragma unroll
        for (int a = 0; a < 4; a++)
#pragma unroll
            for (int c = 0; c < 4; c++) accS[a][c] = 0ull;

#pragma unroll 4
        for (int d = 0; d < 64; d++) {
            u64 kd[4];
#pragma unroll
            for (int c = 0; c < 4; c++) kd[c] = dup2(Kt[d * XT_LD + lane + 32 * c]);
#pragma unroll
            for (int rp = 0; rp < 4; rp++) {
                u64 q2 = *(const u64*)&Qt[d * XT_LD + f0 + 2 * rp];
                fma2(accS[rp][0], q2, kd[0]);
                fma2(accS[rp][1], q2, kd[1]);
                fma2(accS[rp][2], q2, kd[2]);
                fma2(accS[rp][3], q2, kd[3]);
            }
        }

        // sigmoid(S/8), store duplicated into Asd
#pragma unroll
        for (int rp = 0; rp < 4; rp++)
#pragma unroll
            for (int c = 0; c < 4; c++) {
                float sa, sb;
                upk2(accS[rp][c], sa, sb);
                float aa = 1.0f / (1.0f + __expf(-0.125f * sa));
                float ab = 1.0f / (1.0f + __expf(-0.125f * sb));
                int g = lane + 32 * c;
                *(u64*)&Asd[(l0 + 2 * rp) * ASD_LD + 2 * g] = dup2(aa);
                *(u64*)&Asd[(l0 + 2 * rp + 1) * ASD_LD + 2 * g] = dup2(ab);
            }
        __syncwarp();

        // O = A K: accO[r] = (O[f0+r][2*lane], O[f0+r][2*lane+1])
        u64 accO[8];
#pragma unroll
        for (int r = 0; r < 8; r++) accO[r] = 0ull;

#pragma unroll 2
        for (int g = 0; g < 128; g += 2) {
            u64 k20 = *(const u64*)&Ks[g * 64 + 2 * lane];
            u64 k21 = *(const u64*)&Ks[(g + 1) * 64 + 2 * lane];
#pragma unroll
            for (int r = 0; r < 8; r++) {
                ulonglong2 a2 = *(const ulonglong2*)&Asd[(l0 + r) * ASD_LD + 2 * g];
                fma2(accO[r], a2.x, k20);
                fma2(accO[r], a2.y, k21);
            }
        }

        // LayerNorm each row + store (first tuple element)
#pragma unroll
        for (int r = 0; r < 8; r++) {
            float o0, o1;
            upk2(accO[r], o0, o1);
            float s = o0 + o1;
            float ss = o0 * o0 + o1 * o1;
#pragma unroll
            for (int off = 16; off; off >>= 1) {
                s += __shfl_xor_sync(0xFFFFFFFFu, s, off);
                ss += __shfl_xor_sync(0xFFFFFFFFu, ss, off);
            }
            float mu = s * (1.0f / 64.0f);
            float var = ss * (1.0f / 64.0f) - mu * mu;
            float sc = rsqrtf(var + 1e-3f);
            int f = f0 + r;
            float2 ov;
            ov.x = (o0 - mu) * sc * g0 + be0;
            ov.y = (o1 - mu) * sc * g1 + be1;
            *(float2*)&out[(((size_t)h * B + b) * F + f) * 64 + 2 * lane] = ov;
        }
        __syncwarp();   // Asd reuse safety for next pass
    }
}

extern "C" void kernel_launch(void* const* d_in, const int* in_sizes, int n_in,
                              void* d_out, int out_size) {
    const float* x     = (const float*)d_in[0];
    const float* wq    = (const float*)d_in[1];
    const float* wk    = (const float*)d_in[2];
    const float* wr    = (const float*)d_in[3];
    const float* gamma = (const float*)d_in[4];
    const float* beta  = (const float*)d_in[5];
    float* out = (float*)d_out;

    int B = in_sizes[0] / (F * DIN);

    cudaFuncSetAttribute(mha_sigmoid_ln_kernel,
                         cudaFuncAttributeMaxDynamicSharedMemorySize,
                         SMEM_FLOATS * (int)sizeof(float));

    dim3 grid(H, B);
    mha_sigmoid_ln_kernel<<<grid, 256, SMEM_FLOATS * sizeof(float)>>>(
        x, wq, wk, wr, gamma, beta, out, B);
}

// round 5
// speedup vs baseline: 2.3831x; 2.3831x over previous
#include <cuda_runtime.h>
#include <cstdint>

typedef unsigned int u32;
typedef unsigned long long u64;
#define DEVINL __device__ __forceinline__

constexpr int F = 128, DIN = 64, D = 64, H = 8;

// smem byte offsets; 64-col bf16 arrays use stride 144B, 128-col use 272B
constexpr u32 SB64 = 144, SB128 = 272;
constexpr u32 XH = 0;               // X hi  [128][64] (+pad)
constexpr u32 XL = 18432;           // X lo
constexpr u32 WH = 36864;           // W^T hi [64][64] (d-major rows, k=i)
constexpr u32 WL = 46080;           // W^T lo
constexpr u32 QH = 55296;           // Q hi [128][64]
constexpr u32 QL = 73728;
constexpr u32 KH = 92160;           // K hi [128][64]
constexpr u32 KL = 110592;
// sigmoid-A [128][128] hi/lo aliased over dead X/W/Q regions
constexpr u32 AH = 0;               // 34816 B (over X)
constexpr u32 AL = 36864;           // 34816 B (over W + part of Q)
constexpr u32 GB = 129024;          // gamma[64] f32, beta[64] f32
constexpr u32 SMEM_TOTAL = 129536;

DEVINL u32 s2u(const void* p) {
    u32 a; asm("{ .reg .u64 t; cvta.to.shared.u64 t, %1; cvt.u32.u64 %0, t; }" : "=r"(a) : "l"(p));
    return a;
}
DEVINL void ldsm4(u32& r0, u32& r1, u32& r2, u32& r3, u32 a) {
    asm volatile("ldmatrix.sync.aligned.m8n8.x4.shared.b16 {%0,%1,%2,%3}, [%4];"
                 : "=r"(r0), "=r"(r1), "=r"(r2), "=r"(r3) : "r"(a));
}
DEVINL void ldsm4t(u32& r0, u32& r1, u32& r2, u32& r3, u32 a) {
    asm volatile("ldmatrix.sync.aligned.m8n8.x4.trans.shared.b16 {%0,%1,%2,%3}, [%4];"
                 : "=r"(r0), "=r"(r1), "=r"(r2), "=r"(r3) : "r"(a));
}
DEVINL void mma16816(float* c, u32 a0, u32 a1, u32 a2, u32 a3, u32 b0, u32 b1) {
    asm volatile("mma.sync.aligned.m16n8k16.row.col.f32.bf16.bf16.f32 "
                 "{%0,%1,%2,%3}, {%4,%5,%6,%7}, {%8,%9}, {%0,%1,%2,%3};"
                 : "+f"(c[0]), "+f"(c[1]), "+f"(c[2]), "+f"(c[3])
                 : "r"(a0), "r"(a1), "r"(a2), "r"(a3), "r"(b0), "r"(b1));
}
// pack two floats -> bf16x2 (x in low half, y in high half)
DEVINL u32 cvt2(float x, float y) {
    u32 r; asm("cvt.rn.bf16x2.f32 %0, %1, %2;" : "=r"(r) : "f"(y), "f"(x)); return r;
}
DEVINL void split2(float x, float y, u32& hi, u32& lo) {
    hi = cvt2(x, y);
    float rx = x - __uint_as_float(hi << 16);
    float ry = y - __uint_as_float(hi & 0xFFFF0000u);
    lo = cvt2(rx, ry);
}

struct Lane {
    u32 aoff;   // A-ldsm: (lane&15)*stride-part handled per-call; store row/half
    int lr16, lh;   // A addressing
    int bn, bk;     // B plain addressing
    int tg, td;     // B trans addressing
    int qr, qc;     // C fragment row/col
};

// 16(M)x64(N)x64(K) projection-style gemm (A row-major stride SB64 at XHb/XLb,
// B [n][k] stride SB64 at WHb/WLb). acc[8][4].
DEVINL void gemm_n64(float (*acc)[4], u32 sb, u32 XHb, u32 XLb, u32 WHb, u32 WLb,
                     int f0, const Lane& L) {
#pragma unroll
    for (int nt = 0; nt < 8; nt++)
#pragma unroll
        for (int j = 0; j < 4; j++) acc[nt][j] = 0.f;
#pragma unroll
    for (int ks = 0; ks < 4; ks++) {
        u32 aA = sb + (u32)((f0 + L.lr16) * SB64 + 32 * ks + L.lh * 16);
        u32 ah0, ah1, ah2, ah3, al0, al1, al2, al3;
        ldsm4(ah0, ah1, ah2, ah3, aA + XHb);
        ldsm4(al0, al1, al2, al3, aA + XLb);
#pragma unroll
        for (int n2 = 0; n2 < 4; n2++) {
            u32 aB = sb + (u32)((16 * n2 + L.bn) * SB64 + 32 * ks + L.bk * 16);
            u32 bh0, bh1, bh2, bh3, bl0, bl1, bl2, bl3;
            ldsm4(bh0, bh1, bh2, bh3, aB + WHb);
            ldsm4(bl0, bl1, bl2, bl3, aB + WLb);
            mma16816(acc[2 * n2],     ah0, ah1, ah2, ah3, bh0, bh1);
            mma16816(acc[2 * n2 + 1], ah0, ah1, ah2, ah3, bh2, bh3);
            mma16816(acc[2 * n2],     ah0, ah1, ah2, ah3, bl0, bl1);
            mma16816(acc[2 * n2 + 1], ah0, ah1, ah2, ah3, bl2, bl3);
            mma16816(acc[2 * n2],     al0, al1, al2, al3, bh0, bh1);
            mma16816(acc[2 * n2 + 1], al0, al1, al2, al3, bh2, bh3);
        }
    }
}

// store 16x64 fragment as split bf16 hi/lo into [row][col] stride SB64 buffers
DEVINL void store_split64(const float (*acc)[4], u32 sb, u32 BH, u32 BL,
                          int f0, const Lane& L) {
#pragma unroll
    for (int nt = 0; nt < 8; nt++) {
        int c = 8 * nt + L.qc;
        int r1 = f0 + L.qr;
        u32 hi, lo;
        split2(acc[nt][0], acc[nt][1], hi, lo);
        *(u32*)(u64)(sb + BH + r1 * SB64 + c * 2) = hi;   // dummy; replaced below
    }
}

__global__ void __launch_bounds__(256, 1)
mha_hmma_kernel(const float* __restrict__ x,
                const float* __restrict__ wq,
                const float* __restrict__ wk,
                const float* __restrict__ wr,
                const float* __restrict__ gamma,
                const float* __restrict__ beta,
                float* __restrict__ out, int B) {
    extern __shared__ __align__(1024) char sm[];
    const u32 sb = s2u(sm);
    const int tid = threadIdx.x;
    const int w = tid >> 5, lane = tid & 31;
    const int h = blockIdx.x, b = blockIdx.y;
    const int f0 = w * 16;
    const size_t HBFD = (size_t)H * B * F * D;

    Lane L;
    L.lr16 = lane & 15; L.lh = lane >> 4;
    L.bn = (lane & 7) + ((lane >> 4) & 1) * 8; L.bk = (lane >> 3) & 1;
    L.tg = (lane & 7) + ((lane >> 3) & 1) * 8; L.td = ((lane >> 4) & 1) * 8;
    L.qr = lane >> 2; L.qc = (lane & 3) * 2;

    float* const gmS = (float*)(sm + GB);        // gamma[0..63], beta[64..127]
    if (tid < 128) gmS[tid] = (tid < 64) ? gamma[tid] : beta[tid - 64];

    // ---- X[b] -> bf16 hi/lo [f][i] ----
    {
        const float4* xg = (const float4*)(x + (size_t)b * F * DIN);
#pragma unroll
        for (int k = 0; k < 8; k++) {
            int idx4 = tid + 256 * k;
            int f = idx4 >> 4, i4 = (idx4 & 15) * 4;
            float4 v = xg[idx4];
            u32 h0, l0, h1, l1;
            split2(v.x, v.y, h0, l0);
            split2(v.z, v.w, h1, l1);
            u32 off = (u32)(f * SB64 + i4 * 2);
            *(uint2*)(sm + XH + off) = make_uint2(h0, h1);
            *(uint2*)(sm + XL + off) = make_uint2(l0, l1);
        }
    }

    // W loader (transpose to [d][i], split hi/lo)
    auto loadW = [&](const float* __restrict__ wp) {
#pragma unroll
        for (int it = 0; it < 8; it++) {
            int i = 2 * (4 * it + (tid >> 6));
            int d = tid & 63;
            float w0 = wp[i * (H * D) + h * D + d];
            float w1 = wp[(i + 1) * (H * D) + h * D + d];
            u32 hi, lo;
            split2(w0, w1, hi, lo);
            *(u32*)(sm + WH + d * SB64 + i * 2) = hi;
            *(u32*)(sm + WL + d * SB64 + i * 2) = lo;
        }
    };

    float acc[16][4];

    // ================= Q projection =================
    loadW(wq);
    __syncthreads();
    gemm_n64(acc, sb, XH, XL, WH, WL, f0, L);
    // store Q hi/lo
#pragma unroll
    for (int nt = 0; nt < 8; nt++) {
        int c2 = (8 * nt + L.qc) * 2;
        int r1 = f0 + L.qr, r2 = r1 + 8;
        u32 hi, lo;
        split2(acc[nt][0], acc[nt][1], hi, lo);
        *(u32*)(sm + QH + r1 * SB64 + c2) = hi;
        *(u32*)(sm + QL + r1 * SB64 + c2) = lo;
        split2(acc[nt][2], acc[nt][3], hi, lo);
        *(u32*)(sm + QH + r2 * SB64 + c2) = hi;
        *(u32*)(sm + QL + r2 * SB64 + c2) = lo;
    }
    __syncthreads();

    // ================= K projection (V == K per reference) =================
    loadW(wk);
    __syncthreads();
    gemm_n64(acc, sb, XH, XL, WH, WL, f0, L);
#pragma unroll
    for (int nt = 0; nt < 8; nt++) {
        int c2 = (8 * nt + L.qc) * 2;
        int r1 = f0 + L.qr, r2 = r1 + 8;
        u32 hi, lo;
        split2(acc[nt][0], acc[nt][1], hi, lo);
        *(u32*)(sm + KH + r1 * SB64 + c2) = hi;
        *(u32*)(sm + KL + r1 * SB64 + c2) = lo;
        split2(acc[nt][2], acc[nt][3], hi, lo);
        *(u32*)(sm + KH + r2 * SB64 + c2) = hi;
        *(u32*)(sm + KL + r2 * SB64 + c2) = lo;
    }
    __syncthreads();

    // ================= R projection -> direct STG =================
    loadW(wr);
    __syncthreads();
    gemm_n64(acc, sb, XH, XL, WH, WL, f0, L);
    {
        float* o2 = out + HBFD + ((size_t)h * B + b) * (F * D);
#pragma unroll
        for (int nt = 0; nt < 8; nt++) {
            int c = 8 * nt + L.qc;
            int r1 = f0 + L.qr, r2 = r1 + 8;
            *(float2*)(o2 + r1 * 64 + c) = make_float2(acc[nt][0], acc[nt][1]);
            *(float2*)(o2 + r2 * 64 + c) = make_float2(acc[nt][2], acc[nt][3]);
        }
    }

    // ================= S = Q K^T (M=128,N=128,K=64) =================
#pragma unroll
    for (int nt = 0; nt < 16; nt++)
#pragma unroll
        for (int j = 0; j < 4; j++) acc[nt][j] = 0.f;
#pragma unroll
    for (int ks = 0; ks < 4; ks++) {
        u32 aA = sb + (u32)((f0 + L.lr16) * SB64 + 32 * ks + L.lh * 16);
        u32 ah0, ah1, ah2, ah3, al0, al1, al2, al3;
        ldsm4(ah0, ah1, ah2, ah3, aA + QH);
        ldsm4(al0, al1, al2, al3, aA + QL);
#pragma unroll
        for (int n2 = 0; n2 < 8; n2++) {
            u32 aB = sb + (u32)((16 * n2 + L.bn) * SB64 + 32 * ks + L.bk * 16);
            u32 bh0, bh1, bh2, bh3, bl0, bl1, bl2, bl3;
            ldsm4(bh0, bh1, bh2, bh3, aB + KH);
            ldsm4(bl0, bl1, bl2, bl3, aB + KL);
            mma16816(acc[2 * n2],     ah0, ah1, ah2, ah3, bh0, bh1);
            mma16816(acc[2 * n2 + 1], ah0, ah1, ah2, ah3, bh2, bh3);
            mma16816(acc[2 * n2],     ah0, ah1, ah2, ah3, bl0, bl1);
            mma16816(acc[2 * n2 + 1], ah0, ah1, ah2, ah3, bl2, bl3);
            mma16816(acc[2 * n2],     al0, al1, al2, al3, bh0, bh1);
            mma16816(acc[2 * n2 + 1], al0, al1, al2, al3, bh2, bh3);
        }
    }
    __syncthreads();   // all ldsm reads of X/W/Q done before A overwrite

    // ---- sigmoid(S/8) -> split bf16 A[f][g] (stride SB128) ----
#pragma unroll
    for (int nt = 0; nt < 16; nt++) {
        int c2 = (8 * nt + L.qc) * 2;
        int r1 = f0 + L.qr, r2 = r1 + 8;
        float a0 = 1.0f / (1.0f + __expf(-0.125f * acc[nt][0]));
        float a1 = 1.0f / (1.0f + __expf(-0.125f * acc[nt][1]));
        float a2 = 1.0f / (1.0f + __expf(-0.125f * acc[nt][2]));
        float a3 = 1.0f / (1.0f + __expf(-0.125f * acc[nt][3]));
        u32 hi, lo;
        split2(a0, a1, hi, lo);
        *(u32*)(sm + AH + r1 * SB128 + c2) = hi;
        *(u32*)(sm + AL + r1 * SB128 + c2) = lo;
        split2(a2, a3, hi, lo);
        *(u32*)(sm + AH + r2 * SB128 + c2) = hi;
        *(u32*)(sm + AL + r2 * SB128 + c2) = lo;
    }
    __syncthreads();

    // ================= O = A * K (M=128,N=64,K=128), B = K via ldsm.trans =====
    float oc[8][4];
#pragma unroll
    for (int nt = 0; nt < 8; nt++)
#pragma unroll
        for (int j = 0; j < 4; j++) oc[nt][j] = 0.f;
#pragma unroll
    for (int ks = 0; ks < 8; ks++) {
        u32 aA = sb + (u32)((f0 + L.lr16) * SB128 + 32 * ks + L.lh * 16);
        u32 ah0, ah1, ah2, ah3, al0, al1, al2, al3;
        ldsm4(ah0, ah1, ah2, ah3, aA + AH);
        ldsm4(al0, al1, al2, al3, aA + AL);
#pragma unroll
        for (int n2 = 0; n2 < 4; n2++) {
            // B trans: storage rows g = 16ks + tg, cols d = 16n2 + td
            u32 aB = sb + (u32)((16 * ks + L.tg) * SB64 + (16 * n2 + L.td) * 2);
            u32 bh0, bh1, bh2, bh3, bl0, bl1, bl2, bl3;
            ldsm4t(bh0, bh1, bh2, bh3, aB + KH);
            ldsm4t(bl0, bl1, bl2, bl3, aB + KL);
            mma16816(oc[2 * n2],     ah0, ah1, ah2, ah3, bh0, bh1);
            mma16816(oc[2 * n2 + 1], ah0, ah1, ah2, ah3, bh2, bh3);
            mma16816(oc[2 * n2],     ah0, ah1, ah2, ah3, bl0, bl1);
            mma16816(oc[2 * n2 + 1], ah0, ah1, ah2, ah3, bl2, bl3);
            mma16816(oc[2 * n2],     al0, al1, al2, al3, bh0, bh1);
            mma16816(oc[2 * n2 + 1], al0, al1, al2, al3, bh2, bh3);
        }
    }

    // ---- LayerNorm rows + store out1 ----
    {
        float s1 = 0.f, q1 = 0.f, s2 = 0.f, q2 = 0.f;
#pragma unroll
        for (int nt = 0; nt < 8; nt++) {
            s1 += oc[nt][0] + oc[nt][1];
            q1 += oc[nt][0] * oc[nt][0] + oc[nt][1] * oc[nt][1];
            s2 += oc[nt][2] + oc[nt][3];
            q2 += oc[nt][2] * oc[nt][2] + oc[nt][3] * oc[nt][3];
        }
#pragma unroll
        for (int off = 1; off <= 2; off <<= 1) {
            s1 += __shfl_xor_sync(0xFFFFFFFFu, s1, off);
            q1 += __shfl_xor_sync(0xFFFFFFFFu, q1, off);
            s2 += __shfl_xor_sync(0xFFFFFFFFu, s2, off);
            q2 += __shfl_xor_sync(0xFFFFFFFFu, q2, off);
        }
        float mu1 = s1 * (1.0f / 64.0f);
        float v1 = q1 * (1.0f / 64.0f) - mu1 * mu1;
        float sc1 = rsqrtf(v1 + 1e-3f);
        float mu2 = s2 * (1.0f / 64.0f);
        float v2 = q2 * (1.0f / 64.0f) - mu2 * mu2;
        float sc2 = rsqrtf(v2 + 1e-3f);

        float* o1 = out + ((size_t)h * B + b) * (F * D);
        int r1 = f0 + L.qr, r2 = r1 + 8;
#pragma unroll
        for (int nt = 0; nt < 8; nt++) {
            int c = 8 * nt + L.qc;
            float g0 = gmS[c], g1 = gmS[c + 1];
            float b0 = gmS[64 + c], b1 = gmS[64 + c + 1];
            float2 v;
            v.x = (oc[nt][0] - mu1) * sc1 * g0 + b0;
            v.y = (oc[nt][1] - mu1) * sc1 * g1 + b1;
            *(float2*)(o1 + r1 * 64 + c) = v;
            v.x = (oc[nt][2] - mu2) * sc2 * g0 + b0;
            v.y = (oc[nt][3] - mu2) * sc2 * g1 + b1;
            *(float2*)(o1 + r2 * 64 + c) = v;
        }
    }
}

extern "C" void kernel_launch(void* const* d_in, const int* in_sizes, int n_in,
                              void* d_out, int out_size) {
    const float* x     = (const float*)d_in[0];
    const float* wq    = (const float*)d_in[1];
    const float* wk    = (const float*)d_in[2];
    const float* wr    = (const float*)d_in[3];
    const float* gamma = (const float*)d_in[4];
    const float* beta  = (const float*)d_in[5];
    float* out = (float*)d_out;

    int B = in_sizes[0] / (F * DIN);

    cudaFuncSetAttribute(mha_hmma_kernel,
                         cudaFuncAttributeMaxDynamicSharedMemorySize, SMEM_TOTAL);

    dim3 grid(H, B);
    mha_hmma_kernel<<<grid, 256, SMEM_TOTAL>>>(x, wq, wk, wr, gamma, beta, out, B);
}